// round 2
// baseline (speedup 1.0000x reference)
#include <cuda_runtime.h>
#include <cstdint>

#define NDV 100000
#define NE  800000
#define H   128
#define OD  40

// ---------------- device scratch (static globals: allocation-free) -------------
__device__ float g_agg[(size_t)NDV * H];
__device__ float g_out[(size_t)NDV * H];
__device__ float g_h  [(size_t)NDV * H];
__device__ float g_p  [(size_t)NDV * OD];
__device__ float g_deg[NDV];
__device__ float g_inv[NDV];
__device__ float g_sum[H];
__device__ float g_sq [H];
__device__ float g_scale[H];
__device__ float g_shift[H];

// ---------------- helpers: packed f32x2 FMA (sm_100+) --------------------------
__device__ __forceinline__ unsigned long long pk2(float lo, float hi) {
    unsigned long long r;
    asm("mov.b64 %0, {%1,%2};" : "=l"(r) : "f"(lo), "f"(hi));
    return r;
}
__device__ __forceinline__ void upk2(unsigned long long v, float &lo, float &hi) {
    asm("mov.b64 {%0,%1}, %2;" : "=f"(lo), "=f"(hi) : "l"(v));
}
__device__ __forceinline__ void fma2(unsigned long long &c, unsigned long long a, unsigned long long b) {
    asm("fma.rn.f32x2 %0, %1, %2, %0;" : "+l"(c) : "l"(a), "l"(b));
}
__device__ __forceinline__ void red4(float* p, float x, float y, float z, float w) {
    asm volatile("red.global.add.v4.f32 [%0], {%1,%2,%3,%4};"
                 :: "l"(p), "f"(x), "f"(y), "f"(z), "f"(w) : "memory");
}

// ---------------- small kernels ------------------------------------------------
__global__ void k_zero_deg() {
    int i = blockIdx.x * blockDim.x + threadIdx.x;
    if (i < NDV) g_deg[i] = 0.f;
}
__global__ void k_zero_agg() {
    int i = blockIdx.x * blockDim.x + threadIdx.x;
    if (i < NDV * H / 4) ((float4*)g_agg)[i] = make_float4(0.f, 0.f, 0.f, 0.f);
}
__global__ void k_zero_sums() {
    int i = threadIdx.x;
    if (i < H) { g_sum[i] = 0.f; g_sq[i] = 0.f; }
}
__global__ void k_deg(const int* __restrict__ dst) {
    int e = blockIdx.x * blockDim.x + threadIdx.x;
    if (e < NE) atomicAdd(&g_deg[dst[e]], 1.f);
}
__global__ void k_inv() {
    int i = blockIdx.x * blockDim.x + threadIdx.x;
    if (i < NDV) g_inv[i] = 1.f / fmaxf(g_deg[i], 1.f);
}

// warp-per-edge gather of a 128-float row + vector red scatter
__global__ void k_agg(const int* __restrict__ src, const int* __restrict__ dst,
                      const float* __restrict__ hext, int use_gh) {
    int idx = blockIdx.x * blockDim.x + threadIdx.x;
    int e = idx >> 5, lane = idx & 31;
    if (e >= NE) return;
    const float* h = use_gh ? (const float*)g_h : hext;
    int s = src[e], d = dst[e];
    float4 v = ((const float4*)(h + (size_t)s * H))[lane];
    float* o = g_agg + (size_t)d * H + lane * 4;
    red4(o, v.x, v.y, v.z, v.w);
}

// ---------------- layer 0/1 fused GEMM: out = A@Wself + (agg*inv)@Wneigh ------
// persistent CTAs, BM=64, BN=128, K=256; f32x2 row-pair accumulators;
// fused per-column sum/sumsq for BN batch stats.
#define TILES01 ((NDV + 63) / 64)
#define SMEM01  ((256 * 128 + 256 * 64 + 256) * 4)

__global__ __launch_bounds__(256, 1)
void k_gemm01(const float* __restrict__ Aext, int use_gh,
              const float* __restrict__ Wself, const float* __restrict__ Wneigh) {
    extern __shared__ float sm[];
    float* Bs   = sm;                  // [256][128]
    float* As   = sm + 256 * 128;      // [256][64]  (k-major, transposed A tile)
    float* ssum = As + 256 * 64;       // [128]
    float* ssq  = ssum + 128;          // [128]

    const float* A = use_gh ? (const float*)g_h : Aext;
    int tid = threadIdx.x;

    // stage stacked weights once (row-major [k][c], k<128 self / k>=128 neigh)
    for (int i = tid; i < 256 * 128 / 4; i += 256) {
        int e = i * 4, k = e >> 7, c = e & 127;
        float4 v = (k < 128) ? *(const float4*)(Wself + k * H + c)
                             : *(const float4*)(Wneigh + (k - 128) * H + c);
        *(float4*)(Bs + e) = v;
    }
    if (tid < 128) { ssum[tid] = 0.f; ssq[tid] = 0.f; }
    __syncthreads();

    const int r = tid & 63, c0 = tid >> 6;           // A staging mapping
    const int w = tid >> 5, lane = tid & 31;
    const int r0 = w << 3, cc = lane << 2;           // compute mapping
    float csum[4] = {0.f, 0.f, 0.f, 0.f};
    float csq[4]  = {0.f, 0.f, 0.f, 0.f};

    for (int t = blockIdx.x; t < TILES01; t += gridDim.x) {
        int t0 = t * 64;
        __syncthreads();
        // stage A tile transposed: As[k][r] = concat(A_row, agg_row*inv)[k]
        {
            int row = t0 + r;
            bool valid = row < NDV;
            float iv = valid ? g_inv[row] : 0.f;
            const float* arow = A + (size_t)row * H;
            const float* grow = g_agg + (size_t)row * H;
            #pragma unroll
            for (int j = 0; j < 16; ++j) {
                int k = (c0 + (j << 2)) << 2;        // 0..252 step pattern
                float4 v = make_float4(0.f, 0.f, 0.f, 0.f);
                if (valid) {
                    if (k < 128) v = *(const float4*)(arow + k);
                    else {
                        v = *(const float4*)(grow + (k - 128));
                        v.x *= iv; v.y *= iv; v.z *= iv; v.w *= iv;
                    }
                }
                float* p = As + k * 64 + r;
                p[0] = v.x; p[64] = v.y; p[128] = v.z; p[192] = v.w;
            }
        }
        __syncthreads();

        unsigned long long acc[4][4];
        #pragma unroll
        for (int p = 0; p < 4; p++)
            #pragma unroll
            for (int c = 0; c < 4; c++) acc[p][c] = 0ull;

        #pragma unroll 8
        for (int k = 0; k < 256; ++k) {
            float4 alo = *(const float4*)(As + k * 64 + r0);      // rows r0..r0+3 (broadcast)
            float4 ahi = *(const float4*)(As + k * 64 + r0 + 4);  // rows r0+4..r0+7
            float4 bv  = *(const float4*)(Bs + k * 128 + cc);
            unsigned long long a0 = pk2(alo.x, alo.y), a1 = pk2(alo.z, alo.w);
            unsigned long long a2 = pk2(ahi.x, ahi.y), a3 = pk2(ahi.z, ahi.w);
            unsigned long long b0 = pk2(bv.x, bv.x), b1 = pk2(bv.y, bv.y);
            unsigned long long b2 = pk2(bv.z, bv.z), b3 = pk2(bv.w, bv.w);
            fma2(acc[0][0], a0, b0); fma2(acc[0][1], a0, b1);
            fma2(acc[0][2], a0, b2); fma2(acc[0][3], a0, b3);
            fma2(acc[1][0], a1, b0); fma2(acc[1][1], a1, b1);
            fma2(acc[1][2], a1, b2); fma2(acc[1][3], a1, b3);
            fma2(acc[2][0], a2, b0); fma2(acc[2][1], a2, b1);
            fma2(acc[2][2], a2, b2); fma2(acc[2][3], a2, b3);
            fma2(acc[3][0], a3, b0); fma2(acc[3][1], a3, b1);
            fma2(acc[3][2], a3, b2); fma2(acc[3][3], a3, b3);
        }

        // store + BN stat partials (register-resident across tiles)
        #pragma unroll
        for (int p = 0; p < 4; p++) {
            float va[4], vb[4];
            #pragma unroll
            for (int c = 0; c < 4; c++) upk2(acc[p][c], va[c], vb[c]);
            int rowA = t0 + r0 + 2 * p, rowB = rowA + 1;
            if (rowA < NDV) {
                *(float4*)(g_out + (size_t)rowA * H + cc) = make_float4(va[0], va[1], va[2], va[3]);
                #pragma unroll
                for (int c = 0; c < 4; c++) { csum[c] += va[c]; csq[c] += va[c] * va[c]; }
            }
            if (rowB < NDV) {
                *(float4*)(g_out + (size_t)rowB * H + cc) = make_float4(vb[0], vb[1], vb[2], vb[3]);
                #pragma unroll
                for (int c = 0; c < 4; c++) { csum[c] += vb[c]; csq[c] += vb[c] * vb[c]; }
            }
        }
    }

    #pragma unroll
    for (int c = 0; c < 4; c++) {
        atomicAdd(&ssum[cc + c], csum[c]);
        atomicAdd(&ssq[cc + c],  csq[c]);
    }
    __syncthreads();
    if (tid < 128) {
        atomicAdd(&g_sum[tid], ssum[tid]);
        atomicAdd(&g_sq[tid],  ssq[tid]);
    }
}

__global__ void k_bnfin(const float* __restrict__ gamma, const float* __restrict__ beta) {
    int c = threadIdx.x;
    float mean = g_sum[c] * (1.f / NDV);
    float var  = g_sq[c]  * (1.f / NDV) - mean * mean;
    float sc = gamma[c] * rsqrtf(var + 1e-5f);
    g_scale[c] = sc;
    g_shift[c] = beta[c] - mean * sc;
}

__global__ void k_apply() {
    int i = blockIdx.x * blockDim.x + threadIdx.x;   // over N*32 float4s
    if (i >= NDV * 32) return;
    int c4 = i & 31;
    float4 v  = ((const float4*)g_out)[i];
    float4 sc = ((const float4*)g_scale)[c4];
    float4 sh = ((const float4*)g_shift)[c4];
    v.x = fmaxf(fmaf(v.x, sc.x, sh.x), 0.f);
    v.y = fmaxf(fmaf(v.y, sc.y, sh.y), 0.f);
    v.z = fmaxf(fmaf(v.z, sc.z, sh.z), 0.f);
    v.w = fmaxf(fmaf(v.w, sc.w, sh.w), 0.f);
    ((float4*)g_h)[i] = v;
}

// ---------------- layer 2 GEMM: s = h@Ws2 + b2 -> d_out ; p = h@Wn2 -> g_p -----
#define SMEM2 ((128 * 128 + 128 * 64) * 4)

__global__ __launch_bounds__(256, 1)
void k_gemm2(const float* __restrict__ Wself, const float* __restrict__ Wneigh,
             const float* __restrict__ bias, float* __restrict__ out) {
    extern __shared__ float sm[];
    float* Bs = sm;              // [128][128] (cols 0..39 self, 40..79 neigh, rest 0)
    float* As = sm + 128 * 128;  // [128][64]
    int tid = threadIdx.x;

    for (int i = tid; i < 128 * 128 / 4; i += 256) {
        int e = i * 4, k = e >> 7, c = e & 127;
        float4 v = make_float4(0.f, 0.f, 0.f, 0.f);
        if (c < 40)      v = *(const float4*)(Wself  + k * OD + c);
        else if (c < 80) v = *(const float4*)(Wneigh + k * OD + (c - 40));
        *(float4*)(Bs + e) = v;
    }
    __syncthreads();

    const int r = tid & 63, c0 = tid >> 6;
    const int w = tid >> 5, lane = tid & 31;
    const int r0 = w << 3, cc = lane << 2;

    for (int t = blockIdx.x; t < TILES01; t += gridDim.x) {
        int t0 = t * 64;
        __syncthreads();
        {
            int row = t0 + r;
            bool valid = row < NDV;
            const float* arow = g_h + (size_t)row * H;
            #pragma unroll
            for (int j = 0; j < 8; ++j) {
                int k = (c0 + (j << 2)) << 2;    // 0..124
                float4 v = valid ? *(const float4*)(arow + k) : make_float4(0.f, 0.f, 0.f, 0.f);
                float* p = As + k * 64 + r;
                p[0] = v.x; p[64] = v.y; p[128] = v.z; p[192] = v.w;
            }
        }
        __syncthreads();

        unsigned long long acc[4][4];
        #pragma unroll
        for (int p = 0; p < 4; p++)
            #pragma unroll
            for (int c = 0; c < 4; c++) acc[p][c] = 0ull;

        #pragma unroll 8
        for (int k = 0; k < 128; ++k) {
            float4 alo = *(const float4*)(As + k * 64 + r0);
            float4 ahi = *(const float4*)(As + k * 64 + r0 + 4);
            float4 bv  = *(const float4*)(Bs + k * 128 + cc);
            unsigned long long a0 = pk2(alo.x, alo.y), a1 = pk2(alo.z, alo.w);
            unsigned long long a2 = pk2(ahi.x, ahi.y), a3 = pk2(ahi.z, ahi.w);
            unsigned long long b0 = pk2(bv.x, bv.x), b1 = pk2(bv.y, bv.y);
            unsigned long long b2 = pk2(bv.z, bv.z), b3 = pk2(bv.w, bv.w);
            fma2(acc[0][0], a0, b0); fma2(acc[0][1], a0, b1);
            fma2(acc[0][2], a0, b2); fma2(acc[0][3], a0, b3);
            fma2(acc[1][0], a1, b0); fma2(acc[1][1], a1, b1);
            fma2(acc[1][2], a1, b2); fma2(acc[1][3], a1, b3);
            fma2(acc[2][0], a2, b0); fma2(acc[2][1], a2, b1);
            fma2(acc[2][2], a2, b2); fma2(acc[2][3], a2, b3);
            fma2(acc[3][0], a3, b0); fma2(acc[3][1], a3, b1);
            fma2(acc[3][2], a3, b2); fma2(acc[3][3], a3, b3);
        }

        #pragma unroll
        for (int p = 0; p < 4; p++) {
            float va[4], vb[4];
            #pragma unroll
            for (int c = 0; c < 4; c++) upk2(acc[p][c], va[c], vb[c]);
            int rowA = t0 + r0 + 2 * p, rowB = rowA + 1;
            if (rowA < NDV) {
                #pragma unroll
                for (int c = 0; c < 4; c++) {
                    int col = cc + c;
                    if (col < 40)      out[(size_t)rowA * OD + col] = va[c] + bias[col];
                    else if (col < 80) g_p[(size_t)rowA * OD + col - 40] = va[c];
                }
            }
            if (rowB < NDV) {
                #pragma unroll
                for (int c = 0; c < 4; c++) {
                    int col = cc + c;
                    if (col < 40)      out[(size_t)rowB * OD + col] = vb[c] + bias[col];
                    else if (col < 80) g_p[(size_t)rowB * OD + col - 40] = vb[c];
                }
            }
        }
    }
}

// out[dst] += p[src] * inv_deg[dst]  (40 floats/edge = 10 red.v4)
__global__ void k_edge2(const int* __restrict__ src, const int* __restrict__ dst,
                        float* __restrict__ out) {
    int idx = blockIdx.x * blockDim.x + threadIdx.x;
    if (idx >= NE * 10) return;
    int e = idx / 10, c4 = idx - e * 10;
    int s = src[e], d = dst[e];
    float iv = g_inv[d];
    float4 v = *(const float4*)(g_p + (size_t)s * OD + c4 * 4);
    float* o = out + (size_t)d * OD + c4 * 4;
    red4(o, v.x * iv, v.y * iv, v.z * iv, v.w * iv);
}

// ---------------- host launcher ------------------------------------------------
extern "C" void kernel_launch(void* const* d_in, const int* in_sizes, int n_in,
                              void* d_out, int out_size) {
    const float* feat = (const float*)d_in[0];
    const int*   src  = (const int*)d_in[1];
    const int*   dst  = (const int*)d_in[2];
    const float* Ws0 = (const float*)d_in[3];
    const float* Wn0 = (const float*)d_in[4];
    const float* ga0 = (const float*)d_in[5];
    const float* be0 = (const float*)d_in[6];
    const float* Ws1 = (const float*)d_in[7];
    const float* Wn1 = (const float*)d_in[8];
    const float* ga1 = (const float*)d_in[9];
    const float* be1 = (const float*)d_in[10];
    const float* Ws2 = (const float*)d_in[11];
    const float* Wn2 = (const float*)d_in[12];
    const float* b2  = (const float*)d_in[13];
    float* out = (float*)d_out;

    cudaFuncSetAttribute(k_gemm01, cudaFuncAttributeMaxDynamicSharedMemorySize, SMEM01);
    cudaFuncSetAttribute(k_gemm2,  cudaFuncAttributeMaxDynamicSharedMemorySize, SMEM2);

    const int TB = 256;
    // degrees (shared by all layers)
    k_zero_deg<<<(NDV + TB - 1) / TB, TB>>>();
    k_deg<<<(NE + TB - 1) / TB, TB>>>(dst);
    k_inv<<<(NDV + TB - 1) / TB, TB>>>();

    // ---- layer 0 ----
    k_zero_agg<<<(NDV * H / 4 + TB - 1) / TB, TB>>>();
    k_zero_sums<<<1, 128>>>();
    k_agg<<<((size_t)NE * 32 + TB - 1) / TB, TB>>>(src, dst, feat, 0);
    k_gemm01<<<148, 256, SMEM01>>>(feat, 0, Ws0, Wn0);
    k_bnfin<<<1, 128>>>(ga0, be0);
    k_apply<<<(NDV * 32 + TB - 1) / TB, TB>>>();

    // ---- layer 1 ----
    k_zero_agg<<<(NDV * H / 4 + TB - 1) / TB, TB>>>();
    k_zero_sums<<<1, 128>>>();
    k_agg<<<((size_t)NE * 32 + TB - 1) / TB, TB>>>(src, dst, feat, 1);
    k_gemm01<<<148, 256, SMEM01>>>(feat, 1, Ws1, Wn1);
    k_bnfin<<<1, 128>>>(ga1, be1);
    k_apply<<<(NDV * 32 + TB - 1) / TB, TB>>>();

    // ---- layer 2 (project-then-aggregate: 40-wide scatter instead of 128) ----
    k_gemm2<<<148, 256, SMEM2>>>(Ws2, Wn2, b2, out);
    k_edge2<<<((size_t)NE * 10 + TB - 1) / TB, TB>>>(src, dst, out);

    (void)in_sizes; (void)n_in; (void)out_size;
}

// round 4
// speedup vs baseline: 1.1616x; 1.1616x over previous
#include <cuda_runtime.h>
#include <cuda_bf16.h>
#include <cstdint>

#define NDV 100000
#define NE  800000
#define H   128
#define OD  40

// ---------------- device scratch (static globals: allocation-free) -------------
__device__ float g_agg[(size_t)NDV * H];
__device__ float g_out[(size_t)NDV * H];
__device__ float g_h  [(size_t)NDV * H];
__device__ float g_p  [(size_t)NDV * OD];
__device__ float g_deg[NDV];
__device__ float g_inv[NDV];
__device__ float g_sum[H];
__device__ float g_sq [H];
__device__ float g_scale[H];
__device__ float g_shift[H];

// ---------------- helpers ------------------------------------------------------
__device__ __forceinline__ uint32_t s2u(const void* p) {
    uint32_t a;
    asm("{ .reg .u64 t; cvta.to.shared.u64 t, %1; cvt.u32.u64 %0, t; }" : "=r"(a) : "l"(p));
    return a;
}
__device__ __forceinline__ unsigned long long pk2(float lo, float hi) {
    unsigned long long r;
    asm("mov.b64 %0, {%1,%2};" : "=l"(r) : "f"(lo), "f"(hi));
    return r;
}
__device__ __forceinline__ void upk2(unsigned long long v, float &lo, float &hi) {
    asm("mov.b64 {%0,%1}, %2;" : "=f"(lo), "=f"(hi) : "l"(v));
}
__device__ __forceinline__ void fma2(unsigned long long &c, unsigned long long a, unsigned long long b) {
    asm("fma.rn.f32x2 %0, %1, %2, %0;" : "+l"(c) : "l"(a), "l"(b));
}
__device__ __forceinline__ void red4(float* p, float x, float y, float z, float w) {
    asm volatile("red.global.add.v4.f32 [%0], {%1,%2,%3,%4};"
                 :: "l"(p), "f"(x), "f"(y), "f"(z), "f"(w) : "memory");
}
__device__ __forceinline__ uint32_t pkbf(float a, float b) {
    __nv_bfloat162 t = __halves2bfloat162(__float2bfloat16(a), __float2bfloat16(b));
    return *(uint32_t*)&t;
}
__device__ __forceinline__ float bflo(float x) {
    __nv_bfloat16 h = __float2bfloat16(x);
    return x - __bfloat162float(h);
}
__device__ __forceinline__ void ldmA(uint32_t* r, uint32_t a) {
    asm volatile("ldmatrix.sync.aligned.m8n8.x4.shared.b16 {%0,%1,%2,%3},[%4];"
                 : "=r"(r[0]), "=r"(r[1]), "=r"(r[2]), "=r"(r[3]) : "r"(a));
}
__device__ __forceinline__ void ldmBT(uint32_t* r, uint32_t a) {
    asm volatile("ldmatrix.sync.aligned.m8n8.x4.trans.shared.b16 {%0,%1,%2,%3},[%4];"
                 : "=r"(r[0]), "=r"(r[1]), "=r"(r[2]), "=r"(r[3]) : "r"(a));
}
__device__ __forceinline__ void mmabf(float* d, const uint32_t* a, const uint32_t* b) {
    asm volatile("mma.sync.aligned.m16n8k16.row.col.f32.bf16.bf16.f32 "
                 "{%0,%1,%2,%3},{%4,%5,%6,%7},{%8,%9},{%0,%1,%2,%3};"
                 : "+f"(d[0]), "+f"(d[1]), "+f"(d[2]), "+f"(d[3])
                 : "r"(a[0]), "r"(a[1]), "r"(a[2]), "r"(a[3]), "r"(b[0]), "r"(b[1]));
}

// ---------------- small kernels ------------------------------------------------
__global__ void k_zero_deg() {
    int i = blockIdx.x * blockDim.x + threadIdx.x;
    if (i < NDV) g_deg[i] = 0.f;
}
__global__ void k_zero_agg() {
    int i = blockIdx.x * blockDim.x + threadIdx.x;
    if (i < NDV * H / 4) ((float4*)g_agg)[i] = make_float4(0.f, 0.f, 0.f, 0.f);
}
__global__ void k_zero_sums() {
    int i = threadIdx.x;
    if (i < H) { g_sum[i] = 0.f; g_sq[i] = 0.f; }
}
__global__ void k_deg(const int* __restrict__ dst) {
    int e = blockIdx.x * blockDim.x + threadIdx.x;
    if (e < NE) atomicAdd(&g_deg[dst[e]], 1.f);
}
__global__ void k_inv() {
    int i = blockIdx.x * blockDim.x + threadIdx.x;
    if (i < NDV) g_inv[i] = 1.f / fmaxf(g_deg[i], 1.f);
}

// warp-per-edge gather + vector red scatter
__global__ void k_agg(const int* __restrict__ src, const int* __restrict__ dst,
                      const float* __restrict__ hext, int use_gh) {
    int idx = blockIdx.x * blockDim.x + threadIdx.x;
    int e = idx >> 5, lane = idx & 31;
    if (e >= NE) return;
    const float* h = use_gh ? (const float*)g_h : hext;
    int s = src[e], d = dst[e];
    float4 v = ((const float4*)(h + (size_t)s * H))[lane];
    float* o = g_agg + (size_t)d * H + lane * 4;
    red4(o, v.x, v.y, v.z, v.w);
}

// ================= layers 0/1 GEMM via mma.sync bf16 (3-term split) ============
// D[64,128] per tile = concat(h, agg*inv)[64,256] @ stacked W[256,128]
// smem layout (XOR-swizzled 16B chunks): Bhi | Blo | Ahi | Alo
#define T64 ((NDV + 63) >> 6)            // 1563 tiles
#define MM_BHI 0
#define MM_BLO 65536
#define MM_AHI 131072
#define MM_ALO 163840
#define MM_TOT 196608

__global__ __launch_bounds__(256, 1)
void k_gemm01mma(const float* __restrict__ Aext, int use_gh,
                 const float* __restrict__ Wself, const float* __restrict__ Wneigh) {
    extern __shared__ char smem[];
    uint32_t sb = s2u(smem);
    const int tid = threadIdx.x, lane = tid & 31, wid = tid >> 5;
    const float* A = use_gh ? (const float*)g_h : Aext;

    // ---- stage stacked weights hi/lo: [k=256][n=128], row=256B, chunk^= (k&7) --
    for (int it = 0; it < 16; ++it) {
        int idx = tid + (it << 8);           // 0..4095 chunks
        int k = idx >> 4, nc = idx & 15, n0 = nc << 3;
        const float* wsrc = (k < 128) ? (Wself + k * H + n0) : (Wneigh + (k - 128) * H + n0);
        float4 v0 = *(const float4*)(wsrc);
        float4 v1 = *(const float4*)(wsrc + 4);
        uint32_t off = (uint32_t)k * 256 + (uint32_t)((nc ^ (k & 7)) << 4);
        *(uint4*)(smem + MM_BHI + off) = make_uint4(
            pkbf(v0.x, v0.y), pkbf(v0.z, v0.w), pkbf(v1.x, v1.y), pkbf(v1.z, v1.w));
        *(uint4*)(smem + MM_BLO + off) = make_uint4(
            pkbf(bflo(v0.x), bflo(v0.y)), pkbf(bflo(v0.z), bflo(v0.w)),
            pkbf(bflo(v1.x), bflo(v1.y)), pkbf(bflo(v1.z), bflo(v1.w)));
    }
    __syncthreads();

    // ---- per-thread constants ----
    const int wm = wid & 1, wn = wid >> 1;          // warp grid 2(M) x 4(N)
    const int rbase = wm << 5, nbase = wn << 5;     // rows 0/32, cols 0/32/64/96
    const int l7 = lane & 7, kp = lane >> 4, l15 = lane & 15;
    const int g = lane >> 2, tq = lane & 3;
    const uint32_t aRowHi = sb + MM_AHI + (uint32_t)(rbase + l15) * 512;
    const uint32_t aRowLo = aRowHi + (MM_ALO - MM_AHI);
    const int nb0 = (nbase >> 3) + kp;
    const uint32_t bch0 = (uint32_t)((nb0 ^ l7) << 4);
    const uint32_t bch1 = (uint32_t)(((nb0 + 2) ^ l7) << 4);
    const uint32_t bHiBase = sb + MM_BHI + (uint32_t)l15 * 256;
    const uint32_t bLoBase = sb + MM_BLO + (uint32_t)l15 * 256;

    const int srow = tid >> 2, skq = (tid & 3) << 6;   // A staging: row 0..63, k base

    for (int t = blockIdx.x; t < T64; t += gridDim.x) {
        int t0 = t << 6;
        __syncthreads();
        // ---- stage A tile hi/lo: [row=64][k=256], row=512B, chunk ^= (row&7) ---
        {
            int rowg = t0 + srow;
            bool valid = rowg < NDV;
            float iv = (valid && skq >= 128) ? g_inv[rowg] : 1.f;
            const float* srcp = (skq < 128) ? (A + (size_t)rowg * H + skq)
                                            : (g_agg + (size_t)rowg * H + (skq - 128));
            uint32_t rowoff = (uint32_t)srow * 512;
            int rs = srow & 7;
            #pragma unroll
            for (int j = 0; j < 16; ++j) {
                float4 v = valid ? *(const float4*)(srcp + (j << 2))
                                 : make_float4(0.f, 0.f, 0.f, 0.f);
                v.x *= iv; v.y *= iv; v.z *= iv; v.w *= iv;
                int k = skq + (j << 2);
                uint32_t off = rowoff + (uint32_t)(((k >> 3) ^ rs) << 4) + (uint32_t)((k & 7) << 1);
                *(uint2*)(smem + MM_AHI + off) = make_uint2(pkbf(v.x, v.y), pkbf(v.z, v.w));
                *(uint2*)(smem + MM_ALO + off) = make_uint2(pkbf(bflo(v.x), bflo(v.y)),
                                                            pkbf(bflo(v.z), bflo(v.w)));
            }
        }
        __syncthreads();

        // ---- compute: 16 k-steps x 3 terms ----
        float d[2][4][4];
        #pragma unroll
        for (int m = 0; m < 2; ++m)
            #pragma unroll
            for (int nb = 0; nb < 4; ++nb)
                #pragma unroll
                for (int e = 0; e < 4; ++e) d[m][nb][e] = 0.f;

        #pragma unroll 4
        for (int ks = 0; ks < 16; ++ks) {
            uint32_t ach = (uint32_t)((((ks << 1) + kp) ^ l7) << 4);
            uint32_t ahi0[4], ahi1[4], alo0[4], alo1[4];
            ldmA(ahi0, aRowHi + ach);
            ldmA(ahi1, aRowHi + 8192 + ach);
            ldmA(alo0, aRowLo + ach);
            ldmA(alo1, aRowLo + 8192 + ach);
            uint32_t bks = (uint32_t)ks << 12;       // ks*16 rows * 256B
            uint32_t bh0[4], bh1[4], bl0[4], bl1[4];
            ldmBT(bh0, bHiBase + bks + bch0);
            ldmBT(bh1, bHiBase + bks + bch1);
            ldmBT(bl0, bLoBase + bks + bch0);
            ldmBT(bl1, bLoBase + bks + bch1);
            // hi*hi
            mmabf(d[0][0], ahi0, bh0); mmabf(d[0][1], ahi0, bh0 + 2);
            mmabf(d[0][2], ahi0, bh1); mmabf(d[0][3], ahi0, bh1 + 2);
            mmabf(d[1][0], ahi1, bh0); mmabf(d[1][1], ahi1, bh0 + 2);
            mmabf(d[1][2], ahi1, bh1); mmabf(d[1][3], ahi1, bh1 + 2);
            // hi*lo
            mmabf(d[0][0], ahi0, bl0); mmabf(d[0][1], ahi0, bl0 + 2);
            mmabf(d[0][2], ahi0, bl1); mmabf(d[0][3], ahi0, bl1 + 2);
            mmabf(d[1][0], ahi1, bl0); mmabf(d[1][1], ahi1, bl0 + 2);
            mmabf(d[1][2], ahi1, bl1); mmabf(d[1][3], ahi1, bl1 + 2);
            // lo*hi
            mmabf(d[0][0], alo0, bh0); mmabf(d[0][1], alo0, bh0 + 2);
            mmabf(d[0][2], alo0, bh1); mmabf(d[0][3], alo0, bh1 + 2);
            mmabf(d[1][0], alo1, bh0); mmabf(d[1][1], alo1, bh0 + 2);
            mmabf(d[1][2], alo1, bh1); mmabf(d[1][3], alo1, bh1 + 2);
        }

        // ---- epilogue ----
        #pragma unroll
        for (int m = 0; m < 2; ++m) {
            int row0 = t0 + rbase + (m << 4) + g;
            int row1 = row0 + 8;
            if (row0 < NDV) {
                float* o = g_out + (size_t)row0 * H + nbase + (tq << 1);
                #pragma unroll
                for (int nb = 0; nb < 4; ++nb)
                    *(float2*)(o + (nb << 3)) = make_float2(d[m][nb][0], d[m][nb][1]);
            }
            if (row1 < NDV) {
                float* o = g_out + (size_t)row1 * H + nbase + (tq << 1);
                #pragma unroll
                for (int nb = 0; nb < 4; ++nb)
                    *(float2*)(o + (nb << 3)) = make_float2(d[m][nb][2], d[m][nb][3]);
            }
        }
    }
}

// ---------------- BN: column stats over g_out ----------------------------------
__global__ void k_bnstat() {
    __shared__ float ss[H], sq[H];
    int tid = threadIdx.x;
    if (tid < H) { ss[tid] = 0.f; sq[tid] = 0.f; }
    __syncthreads();
    int c4 = tid & 31;
    float4 s = make_float4(0.f, 0.f, 0.f, 0.f), q = make_float4(0.f, 0.f, 0.f, 0.f);
    for (int r = blockIdx.x * 8 + (tid >> 5); r < NDV; r += gridDim.x * 8) {
        float4 v = ((const float4*)g_out)[r * 32 + c4];
        s.x += v.x; s.y += v.y; s.z += v.z; s.w += v.w;
        q.x += v.x * v.x; q.y += v.y * v.y; q.z += v.z * v.z; q.w += v.w * v.w;
    }
    atomicAdd(&ss[c4 * 4 + 0], s.x); atomicAdd(&ss[c4 * 4 + 1], s.y);
    atomicAdd(&ss[c4 * 4 + 2], s.z); atomicAdd(&ss[c4 * 4 + 3], s.w);
    atomicAdd(&sq[c4 * 4 + 0], q.x); atomicAdd(&sq[c4 * 4 + 1], q.y);
    atomicAdd(&sq[c4 * 4 + 2], q.z); atomicAdd(&sq[c4 * 4 + 3], q.w);
    __syncthreads();
    if (tid < H) { atomicAdd(&g_sum[tid], ss[tid]); atomicAdd(&g_sq[tid], sq[tid]); }
}

__global__ void k_bnfin(const float* __restrict__ gamma, const float* __restrict__ beta) {
    int c = threadIdx.x;
    float mean = g_sum[c] * (1.f / NDV);
    float var  = g_sq[c]  * (1.f / NDV) - mean * mean;
    float sc = gamma[c] * rsqrtf(var + 1e-5f);
    g_scale[c] = sc;
    g_shift[c] = beta[c] - mean * sc;
}

__global__ void k_apply() {
    int i = blockIdx.x * blockDim.x + threadIdx.x;
    if (i >= NDV * 32) return;
    int c4 = i & 31;
    float4 v  = ((const float4*)g_out)[i];
    float4 sc = ((const float4*)g_scale)[c4];
    float4 sh = ((const float4*)g_shift)[c4];
    v.x = fmaxf(fmaf(v.x, sc.x, sh.x), 0.f);
    v.y = fmaxf(fmaf(v.y, sc.y, sh.y), 0.f);
    v.z = fmaxf(fmaf(v.z, sc.z, sh.z), 0.f);
    v.w = fmaxf(fmaf(v.w, sc.w, sh.w), 0.f);
    ((float4*)g_h)[i] = v;
}

// ---------------- layer 2 GEMM (FFMA2, known-correct from round 2) -------------
#define TILES64 ((NDV + 63) / 64)
#define SMEM2 ((128 * 128 + 128 * 64) * 4)

__global__ __launch_bounds__(256, 1)
void k_gemm2(const float* __restrict__ Wself, const float* __restrict__ Wneigh,
             const float* __restrict__ bias, float* __restrict__ out) {
    extern __shared__ float sm[];
    float* Bs = sm;              // [128][128] (cols 0..39 self, 40..79 neigh, rest 0)
    float* As = sm + 128 * 128;  // [128][64]
    int tid = threadIdx.x;

    for (int i = tid; i < 128 * 128 / 4; i += 256) {
        int e = i * 4, k = e >> 7, c = e & 127;
        float4 v = make_float4(0.f, 0.f, 0.f, 0.f);
        if (c < 40)      v = *(const float4*)(Wself  + k * OD + c);
        else if (c < 80) v = *(const float4*)(Wneigh + k * OD + (c - 40));
        *(float4*)(Bs + e) = v;
    }
    __syncthreads();

    const int r = tid & 63, c0 = tid >> 6;
    const int w = tid >> 5, lane = tid & 31;
    const int r0 = w << 3, cc = lane << 2;

    for (int t = blockIdx.x; t < TILES64; t += gridDim.x) {
        int t0 = t * 64;
        __syncthreads();
        {
            int row = t0 + r;
            bool valid = row < NDV;
            const float* arow = (const float*)g_h + (size_t)row * H;
            #pragma unroll
            for (int j = 0; j < 8; ++j) {
                int k = (c0 + (j << 2)) << 2;
                float4 v = valid ? *(const float4*)(arow + k) : make_float4(0.f, 0.f, 0.f, 0.f);
                float* p = As + k * 64 + r;
                p[0] = v.x; p[64] = v.y; p[128] = v.z; p[192] = v.w;
            }
        }
        __syncthreads();

        unsigned long long acc[4][4];
        #pragma unroll
        for (int p = 0; p < 4; p++)
            #pragma unroll
            for (int c = 0; c < 4; c++) acc[p][c] = 0ull;

        #pragma unroll 8
        for (int k = 0; k < 128; ++k) {
            float4 alo = *(const float4*)(As + k * 64 + r0);
            float4 ahi = *(const float4*)(As + k * 64 + r0 + 4);
            float4 bv  = *(const float4*)(Bs + k * 128 + cc);
            unsigned long long a0 = pk2(alo.x, alo.y), a1 = pk2(alo.z, alo.w);
            unsigned long long a2 = pk2(ahi.x, ahi.y), a3 = pk2(ahi.z, ahi.w);
            unsigned long long b0 = pk2(bv.x, bv.x), b1 = pk2(bv.y, bv.y);
            unsigned long long b2 = pk2(bv.z, bv.z), b3 = pk2(bv.w, bv.w);
            fma2(acc[0][0], a0, b0); fma2(acc[0][1], a0, b1);
            fma2(acc[0][2], a0, b2); fma2(acc[0][3], a0, b3);
            fma2(acc[1][0], a1, b0); fma2(acc[1][1], a1, b1);
            fma2(acc[1][2], a1, b2); fma2(acc[1][3], a1, b3);
            fma2(acc[2][0], a2, b0); fma2(acc[2][1], a2, b1);
            fma2(acc[2][2], a2, b2); fma2(acc[2][3], a2, b3);
            fma2(acc[3][0], a3, b0); fma2(acc[3][1], a3, b1);
            fma2(acc[3][2], a3, b2); fma2(acc[3][3], a3, b3);
        }

        #pragma unroll
        for (int p = 0; p < 4; p++) {
            float va[4], vb[4];
            #pragma unroll
            for (int c = 0; c < 4; c++) upk2(acc[p][c], va[c], vb[c]);
            int rowA = t0 + r0 + 2 * p, rowB = rowA + 1;
            if (rowA < NDV) {
                #pragma unroll
                for (int c = 0; c < 4; c++) {
                    int col = cc + c;
                    if (col < 40)      out[(size_t)rowA * OD + col] = va[c] + bias[col];
                    else if (col < 80) g_p[(size_t)rowA * OD + col - 40] = va[c];
                }
            }
            if (rowB < NDV) {
                #pragma unroll
                for (int c = 0; c < 4; c++) {
                    int col = cc + c;
                    if (col < 40)      out[(size_t)rowB * OD + col] = vb[c] + bias[col];
                    else if (col < 80) g_p[(size_t)rowB * OD + col - 40] = vb[c];
                }
            }
        }
    }
}

// out[dst] += p[src] * inv_deg[dst]  (40 floats/edge = 10 red.v4)
__global__ void k_edge2(const int* __restrict__ src, const int* __restrict__ dst,
                        float* __restrict__ out) {
    int idx = blockIdx.x * blockDim.x + threadIdx.x;
    if (idx >= NE * 10) return;
    int e = idx / 10, c4 = idx - e * 10;
    int s = src[e], d = dst[e];
    float iv = g_inv[d];
    float4 v = *(const float4*)(g_p + (size_t)s * OD + c4 * 4);
    float* o = out + (size_t)d * OD + c4 * 4;
    red4(o, v.x * iv, v.y * iv, v.z * iv, v.w * iv);
}

// ---------------- host launcher ------------------------------------------------
extern "C" void kernel_launch(void* const* d_in, const int* in_sizes, int n_in,
                              void* d_out, int out_size) {
    const float* feat = (const float*)d_in[0];
    const int*   src  = (const int*)d_in[1];
    const int*   dst  = (const int*)d_in[2];
    const float* Ws0 = (const float*)d_in[3];
    const float* Wn0 = (const float*)d_in[4];
    const float* ga0 = (const float*)d_in[5];
    const float* be0 = (const float*)d_in[6];
    const float* Ws1 = (const float*)d_in[7];
    const float* Wn1 = (const float*)d_in[8];
    const float* ga1 = (const float*)d_in[9];
    const float* be1 = (const float*)d_in[10];
    const float* Ws2 = (const float*)d_in[11];
    const float* Wn2 = (const float*)d_in[12];
    const float* b2  = (const float*)d_in[13];
    float* out = (float*)d_out;

    cudaFuncSetAttribute(k_gemm01mma, cudaFuncAttributeMaxDynamicSharedMemorySize, MM_TOT);
    cudaFuncSetAttribute(k_gemm2,     cudaFuncAttributeMaxDynamicSharedMemorySize, SMEM2);

    const int TB = 256;
    k_zero_deg<<<(NDV + TB - 1) / TB, TB>>>();
    k_deg<<<(NE + TB - 1) / TB, TB>>>(dst);
    k_inv<<<(NDV + TB - 1) / TB, TB>>>();

    // ---- layer 0 ----
    k_zero_agg<<<(NDV * H / 4 + TB - 1) / TB, TB>>>();
    k_agg<<<((size_t)NE * 32 + TB - 1) / TB, TB>>>(src, dst, feat, 0);
    k_gemm01mma<<<148, 256, MM_TOT>>>(feat, 0, Ws0, Wn0);
    k_zero_sums<<<1, 128>>>();
    k_bnstat<<<592, 256>>>();
    k_bnfin<<<1, 128>>>(ga0, be0);
    k_apply<<<(NDV * 32 + TB - 1) / TB, TB>>>();

    // ---- layer 1 ----
    k_zero_agg<<<(NDV * H / 4 + TB - 1) / TB, TB>>>();
    k_agg<<<((size_t)NE * 32 + TB - 1) / TB, TB>>>(src, dst, feat, 1);
    k_gemm01mma<<<148, 256, MM_TOT>>>(feat, 1, Ws1, Wn1);
    k_zero_sums<<<1, 128>>>();
    k_bnstat<<<592, 256>>>();
    k_bnfin<<<1, 128>>>(ga1, be1);
    k_apply<<<(NDV * 32 + TB - 1) / TB, TB>>>();

    // ---- layer 2 (project-then-aggregate: 40-wide scatter instead of 128) ----
    k_gemm2<<<148, 256, SMEM2>>>(Ws2, Wn2, b2, out);
    k_edge2<<<((size_t)NE * 10 + TB - 1) / TB, TB>>>(src, dst, out);

    (void)in_sizes; (void)n_in; (void)out_size;
}